// round 4
// baseline (speedup 1.0000x reference)
#include <cuda_runtime.h>
#include <cstdint>

#define CIN      64
#define COUT     64
#define BATCH    16
#define IM       32
#define LOCS     1024
#define KVOL     576
#define OSTRIDE  589824            // LOCS*KVOL: weight stride between o channels
#define RS       584               // patch smem k-row stride (floats): 16B-aligned, bank-spread
#define NITER    72                // 576 / 8

// ---------------- scratch ----------------
__device__ float g_y[LOCS * 1024];      // [loc][b*64+o]
__device__ float g_psum[LOCS * COUT];
__device__ float g_psumsq[LOCS * COUT];
__device__ float g_scale[COUT];
__device__ float g_shift[COUT];

// ---------------- f32x2 helpers ----------------
__device__ __forceinline__ float2 upk(unsigned long long v) {
    unsigned u0, u1;
    asm("mov.b64 {%0, %1}, %2;" : "=r"(u0), "=r"(u1) : "l"(v));
    return make_float2(__uint_as_float(u0), __uint_as_float(u1));
}
__device__ __forceinline__ void fma2(unsigned long long& d, unsigned long long a,
                                     unsigned long long b) {
    asm("fma.rn.f32x2 %0, %1, %2, %0;" : "+l"(d) : "l"(a), "l"(b));
}

// ---------------- kernel 1: conv + bias + partial stats ----------------
// One CTA (256 threads, 8 warps) per output location. Warp w owns o-range
// [w*8, w*8+8). Lane: ks = lane>>4 (k-split half), og = (lane>>2)&3 (o pair
// index), bg = lane&3 (b = bg + 4*bb). Accumulators packed over adjacent k so
// LDG.128 weight quads feed FFMA2 with no repacking.
__global__ __launch_bounds__(256, 2)
void conv_kernel(const float* __restrict__ x, const float* __restrict__ w,
                 const float* __restrict__ bias) {
    __shared__ __align__(16) float ps[BATCH * RS];   // 37376 B patches [b][k]; reused as ybuf

    const int tid = threadIdx.x;
    const int loc = blockIdx.x;
    const int i0 = loc >> 5, j0 = loc & 31;

    // ---- Phase 1: gather patches ----
    // row r = (b*64+c)*3 + pp  (3072 rows); 4 lanes per row read jj = j0-1+j, keep j<3.
    {
        const int j    = tid & 3;
        const int slot = tid >> 2;                 // 0..63
#pragma unroll 4
        for (int it = 0; it < 48; it++) {
            int r   = slot + (it << 6);
            int b   = r / 192;
            int rem = r - b * 192;
            int c   = rem / 3;
            int pp  = rem - c * 3;
            int ii  = i0 + pp - 1;
            int jj  = j0 - 1 + j;
            float v = 0.0f;
            if ((unsigned)ii < 32u && (unsigned)jj < 32u)
                v = x[((b * 64 + c) * 32 + ii) * 32 + jj];
            if (j <= 2)
                ps[b * RS + c * 9 + pp * 3 + j] = v;
        }
    }
    __syncthreads();

    // ---- Mainloop ----
    const int lane  = tid & 31;
    const int wid   = tid >> 5;
    const int obase = wid * 8;
    const int ks    = lane >> 4;
    const int og    = (lane >> 2) & 3;
    const int bg    = lane & 3;

    const float* pb0 = ps + bg * RS + ks * 4;
    const float* wp0 = w + (size_t)(obase + og * 2) * OSTRIDE + (size_t)loc * KVOL + ks * 4;

    unsigned long long acc[8];                     // acc[oo*4+bb] packed over k
#pragma unroll
    for (int i = 0; i < 8; i++) acc[i] = 0ULL;

    ulonglong2 wc[2], wn[2];
#pragma unroll
    for (int oo = 0; oo < 2; oo++)
        wc[oo] = *(const ulonglong2*)(wp0 + (size_t)oo * OSTRIDE);

#pragma unroll 4
    for (int iter = 0; iter < NITER; iter++) {
        const int knext = (iter < NITER - 1) ? (iter + 1) * 8 : iter * 8;
#pragma unroll
        for (int oo = 0; oo < 2; oo++)
            wn[oo] = *(const ulonglong2*)(wp0 + (size_t)oo * OSTRIDE + knext);

        const int k0 = iter * 8;
#pragma unroll
        for (int bb = 0; bb < 3; bb += 2) {        // (0,1) then (2,3): ILP pairs
            ulonglong2 p0 = *(const ulonglong2*)(pb0 + (bb * 4) * RS + k0);
            ulonglong2 p1 = *(const ulonglong2*)(pb0 + ((bb + 1) * 4) * RS + k0);
#pragma unroll
            for (int oo = 0; oo < 2; oo++) {
                fma2(acc[oo * 4 + bb],     wc[oo].x, p0.x);
                fma2(acc[oo * 4 + bb],     wc[oo].y, p0.y);
                fma2(acc[oo * 4 + bb + 1], wc[oo].x, p1.x);
                fma2(acc[oo * 4 + bb + 1], wc[oo].y, p1.y);
            }
        }
#pragma unroll
        for (int oo = 0; oo < 2; oo++) wc[oo] = wn[oo];
    }

    // ---- Epilogue: k-merge, ks-merge, bias, stats ----
    float yv[8];
#pragma unroll
    for (int i = 0; i < 8; i++) {
        float2 v = upk(acc[i]);
        float f = v.x + v.y;
        f += __shfl_xor_sync(0xffffffffu, f, 16);  // merge the two k-split halves
        yv[i] = f;
    }
    float bz[2];
#pragma unroll
    for (int oo = 0; oo < 2; oo++)
        bz[oo] = bias[(obase + og * 2 + oo) * LOCS + loc];
#pragma unroll
    for (int oo = 0; oo < 2; oo++)
#pragma unroll
        for (int bb = 0; bb < 4; bb++)
            yv[oo * 4 + bb] += bz[oo];

    // per-o partial stats: sum over own 4 b, then across the 4 bg lanes
    float s[2], q2[2];
#pragma unroll
    for (int oo = 0; oo < 2; oo++) {
        float ss = 0.f, qq = 0.f;
#pragma unroll
        for (int bb = 0; bb < 4; bb++) {
            float v = yv[oo * 4 + bb];
            ss += v; qq += v * v;
        }
        ss += __shfl_xor_sync(0xffffffffu, ss, 1);
        qq += __shfl_xor_sync(0xffffffffu, qq, 1);
        ss += __shfl_xor_sync(0xffffffffu, ss, 2);
        qq += __shfl_xor_sync(0xffffffffu, qq, 2);
        s[oo] = ss; q2[oo] = qq;
    }
    if (bg == 0 && ks == 0) {
#pragma unroll
        for (int oo = 0; oo < 2; oo++) {
            int o = obase + og * 2 + oo;
            g_psum[loc * COUT + o]   = s[oo];
            g_psumsq[loc * COUT + o] = q2[oo];
        }
    }

    // ---- y staging + coalesced store ----
    __syncthreads();                               // all warps done reading patches
    float* ybuf = ps;                              // reuse: [b*65 + o], 1040 floats
    if (ks == 0) {
#pragma unroll
        for (int oo = 0; oo < 2; oo++)
#pragma unroll
            for (int bb = 0; bb < 4; bb++) {
                int b = bg + 4 * bb;
                ybuf[b * 65 + obase + og * 2 + oo] = yv[oo * 4 + bb];
            }
    }
    __syncthreads();
#pragma unroll
    for (int rep = 0; rep < 4; rep++) {
        int idx = rep * 256 + tid;                 // 0..1023
        int b = idx >> 6, o = idx & 63;
        g_y[loc * 1024 + idx] = ybuf[b * 65 + o];
    }
}

// ---------------- kernel 2: finalize batch statistics ----------------
__global__ __launch_bounds__(256)
void stats_kernel(const float* __restrict__ gamma, const float* __restrict__ beta) {
    __shared__ float ss[256], sq[256];
    const int o = blockIdx.x, t = threadIdx.x;
    float s = 0.0f, q = 0.0f;
    for (int l = t; l < LOCS; l += 256) {
        s += g_psum[l * COUT + o];
        q += g_psumsq[l * COUT + o];
    }
    ss[t] = s; sq[t] = q;
    __syncthreads();
#pragma unroll
    for (int h = 128; h >= 1; h >>= 1) {
        if (t < h) { ss[t] += ss[t + h]; sq[t] += sq[t + h]; }
        __syncthreads();
    }
    if (t == 0) {
        const float N = (float)(BATCH * LOCS);
        float mean = ss[0] / N;
        float var  = sq[0] / N - mean * mean;
        float sc   = gamma[o] * rsqrtf(var + 1e-5f);
        g_scale[o] = sc;
        g_shift[o] = beta[o] - mean * sc;
    }
}

// ---------------- kernel 3: tiled transpose + BN affine + ReLU ----------------
__global__ __launch_bounds__(256)
void bn_kernel(float* __restrict__ out) {
    __shared__ float tile[32][33];
    __shared__ float s_sc[32], s_sh[32];
    const int t = threadIdx.x;
    const int tx = blockIdx.x;   // bo tile
    const int ty = blockIdx.y;   // loc tile
    if (t < 32) {
        int o = (tx * 32 + t) & 63;
        s_sc[t] = g_scale[o];
        s_sh[t] = g_shift[o];
    }
    const int lr = t >> 5;
    const int lc = t & 31;
#pragma unroll
    for (int p = 0; p < 4; p++) {
        int r = p * 8 + lr;
        tile[r][lc] = g_y[(ty * 32 + r) * 1024 + tx * 32 + lc];
    }
    __syncthreads();
#pragma unroll
    for (int p = 0; p < 4; p++) {
        int r = p * 8 + lr;
        int bo  = tx * 32 + r;
        int loc = ty * 32 + lc;
        float v = tile[lc][r] * s_sc[r] + s_sh[r];
        out[bo * 1024 + loc] = fmaxf(v, 0.0f);
    }
}

// ---------------- launch ----------------
extern "C" void kernel_launch(void* const* d_in, const int* in_sizes, int n_in,
                              void* d_out, int out_size) {
    const float* x     = (const float*)d_in[0];
    const float* w     = (const float*)d_in[1];
    const float* bias  = (const float*)d_in[2];
    const float* gamma = (const float*)d_in[3];
    const float* beta  = (const float*)d_in[4];
    float* out = (float*)d_out;

    conv_kernel<<<LOCS, 256>>>(x, w, bias);
    stats_kernel<<<COUT, 256>>>(gamma, beta);
    bn_kernel<<<dim3(32, 32), 256>>>(out);
}